// round 4
// baseline (speedup 1.0000x reference)
#include <cuda_runtime.h>

// BurstSnn: burst encoder + 2-layer LIF SNN, 32 timesteps.
// x [B,187] f32, W1 [50,187] f32, W2 [5,50] f32
// out: spk_rec [32,B,5] f32 then counts [B] f32
//
// Two samples/warp (16-lane halves).
// Encoder fully precomputed: per-dim 32-bit spike-time mask (bitwise-exact fp
// replay of the reference recurrence), warp-OR'd into per-group step masks.
// Time loop: bit-test -> ballot -> sparse W1 column adds (dual f32x2 chains),
// sparse ballot-gathered layer 2, exact quiescence break at tmax.

#define T_STEPS 32
#define DDIM 187
#define HDIM 50
#define CDIM 5
#define NGRP 12
#define W1PAD 52          // floats per row (208 B)
#define W1TAIL 16         // tail floats so lane-15 128-bit reads stay in-array
#define W2PAD 68          // 272 B rows: avoids 5-way bank conflict on gather

__device__ __forceinline__ void addx2(unsigned long long &a, unsigned long long b) {
    asm("add.rn.f32x2 %0, %1, %2;" : "=l"(a) : "l"(a), "l"(b));
}
__device__ __forceinline__ void mulx2(unsigned long long &a, unsigned long long b) {
    asm("mul.rn.f32x2 %0, %1, %2;" : "=l"(a) : "l"(a), "l"(b));
}
__device__ __forceinline__ unsigned long long packx2(float lo, float hi) {
    unsigned long long r; asm("mov.b64 %0, {%1,%2};" : "=l"(r) : "f"(lo), "f"(hi)); return r;
}
__device__ __forceinline__ void unpackx2(unsigned long long v, float &lo, float &hi) {
    asm("mov.b64 {%0,%1}, %2;" : "=f"(lo), "=f"(hi) : "l"(v));
}

__global__ __launch_bounds__(256, 5)
void burst_snn_kernel(const float* __restrict__ x,
                      const float* __restrict__ W1,
                      const float* __restrict__ W2,
                      float* __restrict__ out, int B)
{
    __shared__ __align__(16) float sW1[DDIM * W1PAD + W1TAIL];  // [d][u] transposed
    __shared__ float sW2[CDIM * W2PAD];

    const int tid = threadIdx.x;
    for (int i = tid; i < DDIM * W1PAD + W1TAIL; i += 256) {
        float v = 0.0f;
        if (i < DDIM * W1PAD) {
            int d = i / W1PAD, u = i - d * W1PAD;
            if (u < HDIM) v = W1[u * DDIM + d];
        }
        sW1[i] = v;
    }
    for (int i = tid; i < CDIM * W2PAD; i += 256) {
        int c = i / W2PAD, h = i - c * W2PAD;
        sW2[i] = (h < HDIM) ? W2[c * HDIM + h] : 0.0f;
    }
    __syncthreads();

    const int lane = tid & 31;
    const int hl   = lane & 15;
    const int half = lane >> 4;
    const int b    = (blockIdx.x * 8 + (tid >> 5)) * 2 + half;
    const bool valid = (b < B);

    // ---------- encoder precompute: spike-time masks (bitwise == reference) ----------
    unsigned mask[NGRP], grpOr[NGRP], allT = 0u;
    int cnt = 0;
    const float* xb = x + (size_t)b * DDIM;
#pragma unroll
    for (int j = 0; j < NGRP; j++) {
        int d = hl + 16 * j;
        float rr = (valid && d < DDIM) ? xb[d] : -1.0f;
        float tt = 0.125f;
        unsigned m = 0u;
        if (rr >= 0.125f) {
#pragma unroll 1
            for (int t = 0; t < T_STEPS; t++) {
                if (rr >= tt) { m |= (1u << t); rr -= tt; tt += tt; }
                else { tt = 0.125f; if (rr < 0.125f) break; }
            }
        }
        mask[j] = m;
        cnt += __popc(m);
        unsigned g = m;
#pragma unroll
        for (int off = 16; off; off >>= 1)
            g |= __shfl_xor_sync(0xffffffffu, g, off);
        grpOr[j] = g;          // warp-wide: steps where ANY lane (either half) spikes
        allT |= g;
    }
    const int tmax = allT ? (31 - __clz(allT)) : -1;

    // validity of this lane's 4 hidden units (4hl..4hl+3)
    const bool v01 = (hl < 13), v23 = (hl < 12);

    unsigned long long m01 = 0ull, m23 = 0ull;   // mem1, packed pairs
    unsigned long long n01 = 0ull, n23 = 0ull;   // alternate accumulation chain
    const unsigned long long BETA2 = packx2(0.9f, 0.9f);
    float m2 = 0.0f;                             // class = hl (lanes hl<5)

    const char*  wb  = (const char*)sW1 + hl * 16;
    const float* w2b = sW2 + hl * W2PAD;
    const int shamt = lane & 16;
    float* po = out + (size_t)b * CDIM + hl;
    const size_t tstride = (size_t)B * CDIM;

    int t = 0;
#pragma unroll 1
    for (; t < T_STEPS; t++) {
        mulx2(m01, BETA2); mulx2(m23, BETA2);
        const unsigned bit = 1u << t;

        if (allT & bit) {
#pragma unroll
            for (int j = 0; j < NGRP; j++) {
                if (!(grpOr[j] & bit)) continue;   // warp-uniform skip
                unsigned bal = __ballot_sync(0xffffffffu, (mask[j] & bit) != 0u);
                unsigned mh = (bal >> shamt) & 0xffffu;
                while (mh) {                       // halves run in lockstep
                    int i0 = __ffs(mh) - 1; mh &= mh - 1;
                    const ulonglong2 w0 = *(const ulonglong2*)(wb + (j * 16 + i0) * 208);
                    if (mh) {
                        int i1 = __ffs(mh) - 1; mh &= mh - 1;
                        const ulonglong2 w1 = *(const ulonglong2*)(wb + (j * 16 + i1) * 208);
                        addx2(m01, w0.x); addx2(m23, w0.y);
                        addx2(n01, w1.x); addx2(n23, w1.y);
                    } else {
                        addx2(m01, w0.x); addx2(m23, w0.y);
                    }
                }
            }
        }

        // -------- LIF1: merge chains, threshold, reset --------
        addx2(m01, n01); addx2(m23, n23);
        n01 = 0ull; n23 = 0ull;
        float a0, a1, a2, a3;
        unpackx2(m01, a0, a1); unpackx2(m23, a2, a3);
        bool s0 = v01 && (a0 > 1.0f), s1 = v01 && (a1 > 1.0f);
        bool s2 = v23 && (a2 > 1.0f), s3 = v23 && (a3 > 1.0f);
        if (s0) a0 -= 1.0f; if (s1) a1 -= 1.0f;
        if (s2) a2 -= 1.0f; if (s3) a3 -= 1.0f;
        m01 = packx2(a0, a1); m23 = packx2(a2, a3);

        // -------- layer 2: ballot-collected sparse gather --------
        unsigned b0 = __ballot_sync(0xffffffffu, s0);
        unsigned b1 = __ballot_sync(0xffffffffu, s1);
        unsigned b2 = __ballot_sync(0xffffffffu, s2);
        unsigned b3 = __ballot_sync(0xffffffffu, s3);
        unsigned anyS1 = b0 | b1 | b2 | b3;

        float cur2 = 0.0f;
        if (anyS1) {
            unsigned f;
            f = (b0 >> shamt) & 0xffffu;
            while (f) { int i = __ffs(f) - 1; f &= f - 1;
                        if (hl < CDIM) cur2 += w2b[4 * i + 0]; }
            f = (b1 >> shamt) & 0xffffu;
            while (f) { int i = __ffs(f) - 1; f &= f - 1;
                        if (hl < CDIM) cur2 += w2b[4 * i + 1]; }
            f = (b2 >> shamt) & 0xffffu;
            while (f) { int i = __ffs(f) - 1; f &= f - 1;
                        if (hl < CDIM) cur2 += w2b[4 * i + 2]; }
            f = (b3 >> shamt) & 0xffffu;
            while (f) { int i = __ffs(f) - 1; f &= f - 1;
                        if (hl < CDIM) cur2 += w2b[4 * i + 3]; }
        }

        // -------- LIF2 + output --------
        m2 = 0.9f * m2 + cur2;
        bool sp2 = (hl < CDIM) && (m2 > 1.0f);
        if (sp2) m2 -= 1.0f;
        if (valid && hl < CDIM) po[(size_t)t * tstride] = sp2 ? 1.0f : 0.0f;

        // -------- exact quiescence: no events past tmax, membranes <= 1 --------
        unsigned anyS2 = __ballot_sync(0xffffffffu, sp2);
        if (t >= tmax && anyS1 == 0u && anyS2 == 0u) { t++; break; }
    }

    if (valid && hl < CDIM)
        for (; t < T_STEPS; t++) po[(size_t)t * tstride] = 0.0f;

    // -------- spike counts (exact integer, reduce within half) --------
#pragma unroll
    for (int off = 8; off; off >>= 1)
        cnt += __shfl_xor_sync(0xffffffffu, cnt, off);
    if (valid && hl == 0)
        out[(size_t)T_STEPS * tstride + b] = (float)cnt;
}

extern "C" void kernel_launch(void* const* d_in, const int* in_sizes, int n_in,
                              void* d_out, int out_size)
{
    const float* x  = (const float*)d_in[0];
    const float* W1 = (const float*)d_in[1];
    const float* W2 = (const float*)d_in[2];
    float* out = (float*)d_out;

    int B = in_sizes[0] / DDIM;
    int blocks = (B + 15) / 16;   // 8 warps/block, 2 samples/warp
    burst_snn_kernel<<<blocks, 256>>>(x, W1, W2, out, B);
}

// round 5
// speedup vs baseline: 1.0004x; 1.0004x over previous
#include <cuda_runtime.h>

// BurstSnn: burst encoder + 2-layer LIF SNN, 32 timesteps.
// x [B,187] f32, W1 [50,187] f32, W2 [5,50] f32
// out: spk_rec [32,B,5] f32 then counts [B] f32
//
// Two samples/warp (16-lane halves). Online burst encoder with dead-group
// skipping (2 consecutive empty ballots => group silent forever). Sparse
// event processing for both layers; software-pipelined LDS in the event loop;
// dual packed-f32x2 accumulator chains; exact quiescence early-exit.

#define T_STEPS 32
#define DDIM 187
#define HDIM 50
#define CDIM 5
#define NGRP 12
#define W1PAD 52          // floats per row (208 B)
#define W1TAIL 16         // tail so lane-15 128-bit reads stay in-array
#define W2PAD 68          // 272 B rows

__device__ __forceinline__ void addx2(unsigned long long &a, unsigned long long b) {
    asm("add.rn.f32x2 %0, %1, %2;" : "=l"(a) : "l"(a), "l"(b));
}
__device__ __forceinline__ void mulx2(unsigned long long &a, unsigned long long b) {
    asm("mul.rn.f32x2 %0, %1, %2;" : "=l"(a) : "l"(a), "l"(b));
}
__device__ __forceinline__ unsigned long long packx2(float lo, float hi) {
    unsigned long long r; asm("mov.b64 %0, {%1,%2};" : "=l"(r) : "f"(lo), "f"(hi)); return r;
}
__device__ __forceinline__ void unpackx2(unsigned long long v, float &lo, float &hi) {
    asm("mov.b64 {%0,%1}, %2;" : "=f"(lo), "=f"(hi) : "l"(v));
}

__global__ __launch_bounds__(256, 5)
void burst_snn_kernel(const float* __restrict__ x,
                      const float* __restrict__ W1,
                      const float* __restrict__ W2,
                      float* __restrict__ out, int B)
{
    __shared__ __align__(16) float sW1[DDIM * W1PAD + W1TAIL];  // [d][u] transposed
    __shared__ float sW2[CDIM * W2PAD];

    const int tid = threadIdx.x;
    for (int i = tid; i < DDIM * W1PAD + W1TAIL; i += 256) {
        float v = 0.0f;
        if (i < DDIM * W1PAD) {
            int d = i / W1PAD, u = i - d * W1PAD;
            if (u < HDIM) v = W1[u * DDIM + d];
        }
        sW1[i] = v;
    }
    for (int i = tid; i < CDIM * W2PAD; i += 256) {
        int c = i / W2PAD, h = i - c * W2PAD;
        sW2[i] = (h < HDIM) ? W2[c * HDIM + h] : 0.0f;
    }
    __syncthreads();

    const int lane = tid & 31;
    const int hl   = lane & 15;
    const int half = lane >> 4;
    const int b    = (blockIdx.x * 8 + (tid >> 5)) * 2 + half;
    const bool valid = (b < B);

    const float INIT_TH = 0.125f;
    const unsigned long long BETA2 = packx2(0.9f, 0.9f);

    // encoder state: dim d = hl + 16*j
    float r[NGRP], th[NGRP];
    const float* xb = x + (size_t)b * DDIM;
#pragma unroll
    for (int j = 0; j < NGRP; j++) {
        int d = hl + 16 * j;
        r[j]  = (valid && d < DDIM) ? xb[d] : -1.0f;   // -1 never spikes
        th[j] = INIT_TH;
    }

    // validity of this lane's 4 hidden units (4hl..4hl+3)
    const bool v01 = (hl < 13), v23 = (hl < 12);

    unsigned long long m01 = 0ull, m23 = 0ull;   // mem1 packed pairs
    unsigned long long n01 = 0ull, n23 = 0ull;   // alternate chain
    float m2 = 0.0f;                             // class = hl (lanes hl<5)
    int cnt = 0;
    unsigned alive = 0xfffu, prevz = 0u;

    const char*  wb  = (const char*)sW1 + hl * 16;
    const float* w2b = sW2 + hl * W2PAD;
    const int shamt = lane & 16;
    float* po = out + (size_t)b * CDIM + hl;
    const size_t tstride = (size_t)B * CDIM;

    int t = 0;
#pragma unroll 1
    for (; t < T_STEPS; t++) {
        mulx2(m01, BETA2); mulx2(m23, BETA2);

        // -------- burst encoder + sparse layer-1 (pipelined) --------
#pragma unroll
        for (int j = 0; j < NGRP; j++) {
            if (!(alive & (1u << j))) continue;          // dead forever
            bool s = (r[j] >= th[j]);
            unsigned bal = __ballot_sync(0xffffffffu, s);
            cnt += s;
            if (s) { r[j] -= th[j]; th[j] *= 2.0f; }
            else   { th[j] = INIT_TH; }
            if (bal == 0u) {
                if (prevz & (1u << j)) alive &= ~(1u << j);
                prevz |= (1u << j);
                continue;
            }
            prevz &= ~(1u << j);
            unsigned mh = (bal >> shamt) & 0xffffu;
            if (mh) {                                    // lockstep across halves
                const char* gb = wb + j * (16 * 208);
                int i0 = __ffs(mh) - 1; mh &= mh - 1;
                ulonglong2 w0 = *(const ulonglong2*)(gb + i0 * 208);
                while (mh) {                             // keep one LDS in flight
                    int i1 = __ffs(mh) - 1; mh &= mh - 1;
                    ulonglong2 w1 = *(const ulonglong2*)(gb + i1 * 208);
                    addx2(m01, w0.x); addx2(m23, w0.y);
                    unsigned long long t01 = n01, t23 = n23;  // rotate chains
                    n01 = m01; n23 = m23; m01 = t01; m23 = t23;
                    w0 = w1;
                }
                addx2(m01, w0.x); addx2(m23, w0.y);
            }
        }

        // -------- LIF1: merge chains, threshold, reset --------
        addx2(m01, n01); addx2(m23, n23);
        n01 = 0ull; n23 = 0ull;
        float a0, a1, a2, a3;
        unpackx2(m01, a0, a1); unpackx2(m23, a2, a3);
        bool s0 = v01 && (a0 > 1.0f), s1 = v01 && (a1 > 1.0f);
        bool s2 = v23 && (a2 > 1.0f), s3 = v23 && (a3 > 1.0f);
        if (s0) a0 -= 1.0f; if (s1) a1 -= 1.0f;
        if (s2) a2 -= 1.0f; if (s3) a3 -= 1.0f;
        m01 = packx2(a0, a1); m23 = packx2(a2, a3);

        // -------- layer 2: ballot-collected sparse gather --------
        unsigned b0 = __ballot_sync(0xffffffffu, s0);
        unsigned b1 = __ballot_sync(0xffffffffu, s1);
        unsigned b2 = __ballot_sync(0xffffffffu, s2);
        unsigned b3 = __ballot_sync(0xffffffffu, s3);
        unsigned anyS1 = b0 | b1 | b2 | b3;

        float cur2 = 0.0f;
        if (anyS1) {
            unsigned f;
            f = (b0 >> shamt) & 0xffffu;
            while (f) { int i = __ffs(f) - 1; f &= f - 1;
                        if (hl < CDIM) cur2 += w2b[4 * i + 0]; }
            f = (b1 >> shamt) & 0xffffu;
            while (f) { int i = __ffs(f) - 1; f &= f - 1;
                        if (hl < CDIM) cur2 += w2b[4 * i + 1]; }
            f = (b2 >> shamt) & 0xffffu;
            while (f) { int i = __ffs(f) - 1; f &= f - 1;
                        if (hl < CDIM) cur2 += w2b[4 * i + 2]; }
            f = (b3 >> shamt) & 0xffffu;
            while (f) { int i = __ffs(f) - 1; f &= f - 1;
                        if (hl < CDIM) cur2 += w2b[4 * i + 3]; }
        }

        // -------- LIF2 + output --------
        m2 = 0.9f * m2 + cur2;
        bool sp2 = (hl < CDIM) && (m2 > 1.0f);
        if (sp2) m2 -= 1.0f;
        if (valid && hl < CDIM) po[(size_t)t * tstride] = sp2 ? 1.0f : 0.0f;

        // -------- quiescence: everything zero from here on --------
        unsigned anyS2 = __ballot_sync(0xffffffffu, sp2);
        if (alive == 0u && anyS1 == 0u && anyS2 == 0u) { t++; break; }
    }

    // zero-fill remaining steps
    if (valid && hl < CDIM)
        for (; t < T_STEPS; t++) po[(size_t)t * tstride] = 0.0f;

    // -------- spike counts (exact integer, reduce within half) --------
#pragma unroll
    for (int off = 8; off; off >>= 1)
        cnt += __shfl_xor_sync(0xffffffffu, cnt, off);
    if (valid && hl == 0)
        out[(size_t)T_STEPS * tstride + b] = (float)cnt;
}

extern "C" void kernel_launch(void* const* d_in, const int* in_sizes, int n_in,
                              void* d_out, int out_size)
{
    const float* x  = (const float*)d_in[0];
    const float* W1 = (const float*)d_in[1];
    const float* W2 = (const float*)d_in[2];
    float* out = (float*)d_out;

    int B = in_sizes[0] / DDIM;
    int blocks = (B + 15) / 16;   // 8 warps/block, 2 samples/warp
    burst_snn_kernel<<<blocks, 256>>>(x, W1, W2, out, B);
}

// round 6
// speedup vs baseline: 1.0799x; 1.0794x over previous
#include <cuda_runtime.h>

// BurstSnn: burst encoder + 2-layer LIF SNN, 32 timesteps.
// x [B,187] f32, W1 [50,187] f32, W2 [5,50] f32
// out: spk_rec [32,B,5] f32 then counts [B] f32
//
// Two samples/warp (16-lane halves). Online burst encoder with dead-group
// skipping. Sparse event processing both layers (R3 loop body: pair-unrolled
// LDS, single accumulator chain). 40KB smem + <=51 regs -> 5 blocks/SM.

#define T_STEPS 32
#define DDIM 187
#define HDIM 50
#define CDIM 5
#define NGRP 12
#define W1PAD 52          // floats per row (208 B)
#define W1TAIL 16         // tail so lane-15 128-bit reads stay in-array
#define W2PAD 68          // 272 B rows

__device__ __forceinline__ void addx2(unsigned long long &a, unsigned long long b) {
    asm("add.rn.f32x2 %0, %1, %2;" : "=l"(a) : "l"(a), "l"(b));
}
__device__ __forceinline__ void mulx2(unsigned long long &a, unsigned long long b) {
    asm("mul.rn.f32x2 %0, %1, %2;" : "=l"(a) : "l"(a), "l"(b));
}
__device__ __forceinline__ unsigned long long packx2(float lo, float hi) {
    unsigned long long r; asm("mov.b64 %0, {%1,%2};" : "=l"(r) : "f"(lo), "f"(hi)); return r;
}
__device__ __forceinline__ void unpackx2(unsigned long long v, float &lo, float &hi) {
    asm("mov.b64 {%0,%1}, %2;" : "=f"(lo), "=f"(hi) : "l"(v));
}

__global__ __launch_bounds__(256, 5)
void burst_snn_kernel(const float* __restrict__ x,
                      const float* __restrict__ W1,
                      const float* __restrict__ W2,
                      float* __restrict__ out, int B)
{
    __shared__ __align__(16) float sW1[DDIM * W1PAD + W1TAIL];  // [d][u] transposed
    __shared__ float sW2[CDIM * W2PAD];

    const int tid = threadIdx.x;
    for (int i = tid; i < DDIM * W1PAD + W1TAIL; i += 256) {
        float v = 0.0f;
        if (i < DDIM * W1PAD) {
            int d = i / W1PAD, u = i - d * W1PAD;
            if (u < HDIM) v = W1[u * DDIM + d];
        }
        sW1[i] = v;
    }
    for (int i = tid; i < CDIM * W2PAD; i += 256) {
        int c = i / W2PAD, h = i - c * W2PAD;
        sW2[i] = (h < HDIM) ? W2[c * HDIM + h] : 0.0f;
    }
    __syncthreads();

    const int lane = tid & 31;
    const int hl   = lane & 15;
    const int half = lane >> 4;
    const int b    = (blockIdx.x * 8 + (tid >> 5)) * 2 + half;
    const bool valid = (b < B);

    const float INIT_TH = 0.125f;
    const unsigned long long BETA2 = packx2(0.9f, 0.9f);

    // encoder state: dim d = hl + 16*j
    float r[NGRP], th[NGRP];
    const float* xb = x + (size_t)b * DDIM;
#pragma unroll
    for (int j = 0; j < NGRP; j++) {
        int d = hl + 16 * j;
        r[j]  = (valid && d < DDIM) ? xb[d] : -1.0f;   // -1 never spikes
        th[j] = INIT_TH;
    }

    // validity of this lane's 4 hidden units (4hl..4hl+3)
    const bool v01 = (hl < 13), v23 = (hl < 12);

    unsigned long long m01 = 0ull, m23 = 0ull;   // mem1 packed pairs
    float m2 = 0.0f;                             // class = hl (lanes hl<5)
    int cnt = 0;
    unsigned alive = 0xfffu, prevz = 0u;

    const char*  wb  = (const char*)sW1 + hl * 16;
    const float* w2b = sW2 + hl * W2PAD;
    const int shamt = lane & 16;
    float* po = out + (size_t)b * CDIM + hl;
    const size_t tstride4 = (size_t)B * CDIM * sizeof(float);

    int t = 0;
#pragma unroll 1
    for (; t < T_STEPS; t++) {
        mulx2(m01, BETA2); mulx2(m23, BETA2);

        // -------- burst encoder + sparse layer-1 (R3 body) --------
#pragma unroll
        for (int j = 0; j < NGRP; j++) {
            if (!(alive & (1u << j))) continue;          // dead forever
            bool s = (r[j] >= th[j]);
            unsigned bal = __ballot_sync(0xffffffffu, s);
            cnt += s;
            if (s) { r[j] -= th[j]; th[j] *= 2.0f; }
            else   { th[j] = INIT_TH; }
            if (bal == 0u) {
                if (prevz & (1u << j)) alive &= ~(1u << j);
                prevz |= (1u << j);
                continue;
            }
            prevz &= ~(1u << j);
            unsigned mh = (bal >> shamt) & 0xffffu;
            const char* gb = wb + j * (16 * 208);
            while (mh) {                                 // lockstep across halves
                int i0 = __ffs(mh) - 1; mh &= mh - 1;
                const ulonglong2 w0 = *(const ulonglong2*)(gb + i0 * 208);
                if (mh) {
                    int i1 = __ffs(mh) - 1; mh &= mh - 1;
                    const ulonglong2 w1 = *(const ulonglong2*)(gb + i1 * 208);
                    addx2(m01, w0.x); addx2(m23, w0.y);
                    addx2(m01, w1.x); addx2(m23, w1.y);
                } else {
                    addx2(m01, w0.x); addx2(m23, w0.y);
                }
            }
        }

        // -------- LIF1 threshold / reset --------
        float a0, a1, a2, a3;
        unpackx2(m01, a0, a1); unpackx2(m23, a2, a3);
        bool s0 = v01 && (a0 > 1.0f), s1 = v01 && (a1 > 1.0f);
        bool s2 = v23 && (a2 > 1.0f), s3 = v23 && (a3 > 1.0f);
        if (s0) a0 -= 1.0f; if (s1) a1 -= 1.0f;
        if (s2) a2 -= 1.0f; if (s3) a3 -= 1.0f;
        m01 = packx2(a0, a1); m23 = packx2(a2, a3);

        // -------- layer 2: ballot-collected sparse gather --------
        unsigned b0 = __ballot_sync(0xffffffffu, s0);
        unsigned b1 = __ballot_sync(0xffffffffu, s1);
        unsigned b2 = __ballot_sync(0xffffffffu, s2);
        unsigned b3 = __ballot_sync(0xffffffffu, s3);
        unsigned anyS1 = b0 | b1 | b2 | b3;

        float cur2 = 0.0f;
        if (anyS1) {
            unsigned f;
            f = (b0 >> shamt) & 0xffffu;
            while (f) { int i = __ffs(f) - 1; f &= f - 1;
                        if (hl < CDIM) cur2 += w2b[4 * i + 0]; }
            f = (b1 >> shamt) & 0xffffu;
            while (f) { int i = __ffs(f) - 1; f &= f - 1;
                        if (hl < CDIM) cur2 += w2b[4 * i + 1]; }
            f = (b2 >> shamt) & 0xffffu;
            while (f) { int i = __ffs(f) - 1; f &= f - 1;
                        if (hl < CDIM) cur2 += w2b[4 * i + 2]; }
            f = (b3 >> shamt) & 0xffffu;
            while (f) { int i = __ffs(f) - 1; f &= f - 1;
                        if (hl < CDIM) cur2 += w2b[4 * i + 3]; }
        }

        // -------- LIF2 + output --------
        m2 = 0.9f * m2 + cur2;
        bool sp2 = (hl < CDIM) && (m2 > 1.0f);
        if (sp2) m2 -= 1.0f;
        if (valid && hl < CDIM) *po = sp2 ? 1.0f : 0.0f;
        po = (float*)((char*)po + tstride4);

        // -------- quiescence: everything zero from here on --------
        unsigned anyS2 = __ballot_sync(0xffffffffu, sp2);
        if (alive == 0u && anyS1 == 0u && anyS2 == 0u) { t++; break; }
    }

    // zero-fill remaining steps
    if (valid && hl < CDIM)
        for (; t < T_STEPS; t++) {
            *po = 0.0f;
            po = (float*)((char*)po + tstride4);
        }

    // -------- spike counts (exact integer, reduce within half) --------
#pragma unroll
    for (int off = 8; off; off >>= 1)
        cnt += __shfl_xor_sync(0xffffffffu, cnt, off);
    if (valid && hl == 0)
        out[(size_t)T_STEPS * B * CDIM + b] = (float)cnt;
}

extern "C" void kernel_launch(void* const* d_in, const int* in_sizes, int n_in,
                              void* d_out, int out_size)
{
    const float* x  = (const float*)d_in[0];
    const float* W1 = (const float*)d_in[1];
    const float* W2 = (const float*)d_in[2];
    float* out = (float*)d_out;

    int B = in_sizes[0] / DDIM;
    int blocks = (B + 15) / 16;   // 8 warps/block, 2 samples/warp
    burst_snn_kernel<<<blocks, 256>>>(x, W1, W2, out, B);
}

// round 7
// speedup vs baseline: 1.1403x; 1.0560x over previous
#include <cuda_runtime.h>

// BurstSnn: burst encoder + 2-layer LIF SNN, 32 timesteps.
// x [B,187] f32, W1 [50,187] f32, W2 [5,50] f32
// out: spk_rec [32,B,5] f32 then counts [B] f32
//
// Two samples/warp (16-lane halves). Online burst encoder with EXACT death
// detection (r < 0.125 => silent forever). Sparse event processing both
// layers. spk_rec is pre-zeroed by cudaMemsetAsync; kernel stores only 1.0s
// and breaks out at quiescence with no fill loop.

#define T_STEPS 32
#define DDIM 187
#define HDIM 50
#define CDIM 5
#define NGRP 12
#define W1PAD 52          // floats per row (208 B)
#define W1TAIL 16         // tail so lane-15 128-bit reads stay in-array
#define W2PAD 68          // 272 B rows

__device__ __forceinline__ void addx2(unsigned long long &a, unsigned long long b) {
    asm("add.rn.f32x2 %0, %1, %2;" : "=l"(a) : "l"(a), "l"(b));
}
__device__ __forceinline__ void mulx2(unsigned long long &a, unsigned long long b) {
    asm("mul.rn.f32x2 %0, %1, %2;" : "=l"(a) : "l"(a), "l"(b));
}
__device__ __forceinline__ unsigned long long packx2(float lo, float hi) {
    unsigned long long r; asm("mov.b64 %0, {%1,%2};" : "=l"(r) : "f"(lo), "f"(hi)); return r;
}
__device__ __forceinline__ void unpackx2(unsigned long long v, float &lo, float &hi) {
    asm("mov.b64 {%0,%1}, %2;" : "=f"(lo), "=f"(hi) : "l"(v));
}

__global__ __launch_bounds__(256, 5)
void burst_snn_kernel(const float* __restrict__ x,
                      const float* __restrict__ W1,
                      const float* __restrict__ W2,
                      float* __restrict__ out, int B)
{
    __shared__ __align__(16) float sW1[DDIM * W1PAD + W1TAIL];  // [d][u] transposed
    __shared__ float sW2[CDIM * W2PAD];

    const int tid = threadIdx.x;
    for (int i = tid; i < DDIM * W1PAD + W1TAIL; i += 256) {
        float v = 0.0f;
        if (i < DDIM * W1PAD) {
            int d = i / W1PAD, u = i - d * W1PAD;
            if (u < HDIM) v = W1[u * DDIM + d];
        }
        sW1[i] = v;
    }
    for (int i = tid; i < CDIM * W2PAD; i += 256) {
        int c = i / W2PAD, h = i - c * W2PAD;
        sW2[i] = (h < HDIM) ? W2[c * HDIM + h] : 0.0f;
    }
    __syncthreads();

    const int lane = tid & 31;
    const int hl   = lane & 15;
    const int half = lane >> 4;
    const int b    = (blockIdx.x * 8 + (tid >> 5)) * 2 + half;
    const bool valid = (b < B);

    const float INIT_TH = 0.125f;
    const unsigned long long BETA2 = packx2(0.9f, 0.9f);

    // encoder state: dim d = hl + 16*j
    float r[NGRP], th[NGRP];
    const float* xb = x + (size_t)b * DDIM;
#pragma unroll
    for (int j = 0; j < NGRP; j++) {
        int d = hl + 16 * j;
        r[j]  = (valid && d < DDIM) ? xb[d] : -1.0f;   // -1 is dead from start
        th[j] = INIT_TH;
    }

    // validity of this lane's 4 hidden units (4hl..4hl+3)
    const bool v01 = (hl < 13), v23 = (hl < 12);

    unsigned long long m01 = 0ull, m23 = 0ull;   // mem1 packed pairs
    float m2 = 0.0f;                             // class = hl (lanes hl<5)
    int cnt = 0;
    unsigned alive = 0xfffu;

    const char*  wb  = (const char*)sW1 + hl * 16;
    const float* w2b = sW2 + hl * W2PAD;
    const int shamt = lane & 16;
    float* po = out + (size_t)b * CDIM + hl;
    const size_t tstride4 = (size_t)B * CDIM * sizeof(float);

#pragma unroll 1
    for (int t = 0; t < T_STEPS; t++) {
        mulx2(m01, BETA2); mulx2(m23, BETA2);

        // -------- burst encoder + sparse layer-1 --------
#pragma unroll
        for (int j = 0; j < NGRP; j++) {
            if (!(alive & (1u << j))) continue;          // dead forever
            bool s = (r[j] >= th[j]);
            unsigned bal = __ballot_sync(0xffffffffu, s);
            cnt += s;
            if (s) { r[j] -= th[j]; th[j] *= 2.0f; }
            else   { th[j] = INIT_TH; }
            // exact death: r < 0.125 can never spike again (th >= 0.125 always)
            unsigned ab = __ballot_sync(0xffffffffu, r[j] >= INIT_TH);
            if (ab == 0u) alive &= ~(1u << j);
            if (bal == 0u) continue;
            unsigned mh = (bal >> shamt) & 0xffffu;
            const char* gb = wb + j * (16 * 208);
            while (mh) {                                 // lockstep across halves
                int i0 = __ffs(mh) - 1; mh &= mh - 1;
                const ulonglong2 w0 = *(const ulonglong2*)(gb + i0 * 208);
                if (mh) {
                    int i1 = __ffs(mh) - 1; mh &= mh - 1;
                    const ulonglong2 w1 = *(const ulonglong2*)(gb + i1 * 208);
                    addx2(m01, w0.x); addx2(m23, w0.y);
                    addx2(m01, w1.x); addx2(m23, w1.y);
                } else {
                    addx2(m01, w0.x); addx2(m23, w0.y);
                }
            }
        }

        // -------- LIF1 threshold / reset --------
        float a0, a1, a2, a3;
        unpackx2(m01, a0, a1); unpackx2(m23, a2, a3);
        bool s0 = v01 && (a0 > 1.0f), s1 = v01 && (a1 > 1.0f);
        bool s2 = v23 && (a2 > 1.0f), s3 = v23 && (a3 > 1.0f);
        if (s0) a0 -= 1.0f; if (s1) a1 -= 1.0f;
        if (s2) a2 -= 1.0f; if (s3) a3 -= 1.0f;
        m01 = packx2(a0, a1); m23 = packx2(a2, a3);

        // -------- layer 2: ballot-collected sparse gather --------
        unsigned b0 = __ballot_sync(0xffffffffu, s0);
        unsigned b1 = __ballot_sync(0xffffffffu, s1);
        unsigned b2 = __ballot_sync(0xffffffffu, s2);
        unsigned b3 = __ballot_sync(0xffffffffu, s3);
        unsigned anyS1 = b0 | b1 | b2 | b3;

        float cur2 = 0.0f;
        if (anyS1) {
            unsigned f;
            f = (b0 >> shamt) & 0xffffu;
            while (f) { int i = __ffs(f) - 1; f &= f - 1;
                        if (hl < CDIM) cur2 += w2b[4 * i + 0]; }
            f = (b1 >> shamt) & 0xffffu;
            while (f) { int i = __ffs(f) - 1; f &= f - 1;
                        if (hl < CDIM) cur2 += w2b[4 * i + 1]; }
            f = (b2 >> shamt) & 0xffffu;
            while (f) { int i = __ffs(f) - 1; f &= f - 1;
                        if (hl < CDIM) cur2 += w2b[4 * i + 2]; }
            f = (b3 >> shamt) & 0xffffu;
            while (f) { int i = __ffs(f) - 1; f &= f - 1;
                        if (hl < CDIM) cur2 += w2b[4 * i + 3]; }
        }

        // -------- LIF2 + output (only 1.0s; zeros pre-set by memset) --------
        m2 = 0.9f * m2 + cur2;
        bool sp2 = (hl < CDIM) && (m2 > 1.0f);
        if (sp2) { m2 -= 1.0f; if (valid) *po = 1.0f; }
        po = (float*)((char*)po + tstride4);

        // -------- quiescence: everything zero from here on --------
        unsigned anyS2 = __ballot_sync(0xffffffffu, sp2);
        if (alive == 0u && anyS1 == 0u && anyS2 == 0u) break;
    }

    // -------- spike counts (exact integer, reduce within half) --------
#pragma unroll
    for (int off = 8; off; off >>= 1)
        cnt += __shfl_xor_sync(0xffffffffu, cnt, off);
    if (valid && hl == 0)
        out[(size_t)T_STEPS * B * CDIM + b] = (float)cnt;
}

extern "C" void kernel_launch(void* const* d_in, const int* in_sizes, int n_in,
                              void* d_out, int out_size)
{
    const float* x  = (const float*)d_in[0];
    const float* W1 = (const float*)d_in[1];
    const float* W2 = (const float*)d_in[2];
    float* out = (float*)d_out;

    int B = in_sizes[0] / DDIM;
    // pre-zero the spk_rec region [32,B,5]; counts are fully written by kernel
    cudaMemsetAsync(out, 0, (size_t)T_STEPS * B * CDIM * sizeof(float));
    int blocks = (B + 15) / 16;   // 8 warps/block, 2 samples/warp
    burst_snn_kernel<<<blocks, 256>>>(x, W1, W2, out, B);
}

// round 8
// speedup vs baseline: 1.4436x; 1.2660x over previous
#include <cuda_runtime.h>

// BurstSnn: burst encoder + 2-layer LIF SNN, 32 timesteps.
// x [B,187] f32, W1 [50,187] f32, W2 [5,50] f32
// out: spk_rec [32,B,5] f32 then counts [B] f32
//
// Two samples/warp (16-lane halves). Sparse event processing both layers.
// t=0,1 peeled with COMPLEMENT accumulation (colsum - nonspikers): those steps
// are ~87%/~62% dense, so iterating non-spikers vs a precomputed W1 column-sum
// is ~6x fewer events. Main loop t>=2 uses lazy exact death detection
// (death ballot only on empty steps). spk_rec pre-zeroed by memset; kernel
// stores only 1.0s and breaks at quiescence.

#define T_STEPS 32
#define DDIM 187
#define HDIM 50
#define CDIM 5
#define NGRP 12
#define W1PAD 52          // floats per W1 row (208 B)
#define W1TAIL 16
#define W2PAD 68          // 272 B rows

__device__ __forceinline__ void addx2(unsigned long long &a, unsigned long long b) {
    asm("add.rn.f32x2 %0, %1, %2;" : "=l"(a) : "l"(a), "l"(b));
}
__device__ __forceinline__ void mulx2(unsigned long long &a, unsigned long long b) {
    asm("mul.rn.f32x2 %0, %1, %2;" : "=l"(a) : "l"(a), "l"(b));
}
__device__ __forceinline__ unsigned long long packx2(float lo, float hi) {
    unsigned long long r; asm("mov.b64 %0, {%1,%2};" : "=l"(r) : "f"(lo), "f"(hi)); return r;
}
__device__ __forceinline__ void unpackx2(unsigned long long v, float &lo, float &hi) {
    asm("mov.b64 {%0,%1}, %2;" : "=f"(lo), "=f"(hi) : "l"(v));
}

// pair-unrolled event accumulation over set bits of mh (warp-lockstep loop)
__device__ __forceinline__ void ev_accum(unsigned mh, const char* gb,
                                         unsigned long long &A01,
                                         unsigned long long &A23) {
    while (mh) {
        int i0 = __ffs(mh) - 1; mh &= mh - 1;
        const ulonglong2 w0 = *(const ulonglong2*)(gb + i0 * 208);
        if (mh) {
            int i1 = __ffs(mh) - 1; mh &= mh - 1;
            const ulonglong2 w1 = *(const ulonglong2*)(gb + i1 * 208);
            addx2(A01, w0.x); addx2(A23, w0.y);
            addx2(A01, w1.x); addx2(A23, w1.y);
        } else {
            addx2(A01, w0.x); addx2(A23, w0.y);
        }
    }
}

// layer-2 sparse gather + LIF2 + store; returns (anyS1|anyS2) for quiescence
__device__ __forceinline__ unsigned step_tail(bool s0, bool s1, bool s2, bool s3,
                                              int hl, int shamt,
                                              const float* __restrict__ w2b,
                                              float &m2, bool valid,
                                              float* &po, size_t tstride4) {
    unsigned b0 = __ballot_sync(0xffffffffu, s0);
    unsigned b1 = __ballot_sync(0xffffffffu, s1);
    unsigned b2 = __ballot_sync(0xffffffffu, s2);
    unsigned b3 = __ballot_sync(0xffffffffu, s3);
    unsigned anyS1 = b0 | b1 | b2 | b3;
    float cur2 = 0.0f;
    if (anyS1) {
        unsigned f;
        f = (b0 >> shamt) & 0xffffu;
        while (f) { int i = __ffs(f) - 1; f &= f - 1;
                    if (hl < CDIM) cur2 += w2b[4 * i + 0]; }
        f = (b1 >> shamt) & 0xffffu;
        while (f) { int i = __ffs(f) - 1; f &= f - 1;
                    if (hl < CDIM) cur2 += w2b[4 * i + 1]; }
        f = (b2 >> shamt) & 0xffffu;
        while (f) { int i = __ffs(f) - 1; f &= f - 1;
                    if (hl < CDIM) cur2 += w2b[4 * i + 2]; }
        f = (b3 >> shamt) & 0xffffu;
        while (f) { int i = __ffs(f) - 1; f &= f - 1;
                    if (hl < CDIM) cur2 += w2b[4 * i + 3]; }
    }
    m2 = 0.9f * m2 + cur2;
    bool sp2 = (hl < CDIM) && (m2 > 1.0f);
    if (sp2) { m2 -= 1.0f; if (valid) *po = 1.0f; }
    po = (float*)((char*)po + tstride4);
    unsigned anyS2 = __ballot_sync(0xffffffffu, sp2);
    return anyS1 | anyS2;
}

__global__ __launch_bounds__(256, 5)
void burst_snn_kernel(const float* __restrict__ x,
                      const float* __restrict__ W1,
                      const float* __restrict__ W2,
                      float* __restrict__ out, int B)
{
    __shared__ __align__(16) float sW1[DDIM * W1PAD + W1TAIL];
    __shared__ float sW2[CDIM * W2PAD];
    __shared__ float sPart[4 * W1PAD];
    __shared__ __align__(16) float sCol[64];      // column sums (pad >= 64 floats)

    const int tid = threadIdx.x;
    for (int i = tid; i < DDIM * W1PAD + W1TAIL; i += 256) {
        float v = 0.0f;
        if (i < DDIM * W1PAD) {
            int d = i / W1PAD, u = i - d * W1PAD;
            if (u < HDIM) v = W1[u * DDIM + d];
        }
        sW1[i] = v;
    }
    for (int i = tid; i < CDIM * W2PAD; i += 256) {
        int c = i / W2PAD, h = i - c * W2PAD;
        sW2[i] = (h < HDIM) ? W2[c * HDIM + h] : 0.0f;
    }
    __syncthreads();

    // ---- column sums of sW1 (52 padded units x 4 segments) ----
    if (tid < 4 * W1PAD) {
        int u = tid % W1PAD, seg = tid / W1PAD;
        float sa = 0.0f, sb = 0.0f;
        int d = seg;
        for (; d + 4 < DDIM; d += 8) {               // dual chains
            sa += sW1[d * W1PAD + u];
            sb += sW1[(d + 4) * W1PAD + u];
        }
        for (; d < DDIM; d += 4) sa += sW1[d * W1PAD + u];
        sPart[seg * W1PAD + u] = sa + sb;
    }
    __syncthreads();
    if (tid < 64) {
        float v = 0.0f;
        if (tid < W1PAD)
            v = sPart[tid] + sPart[W1PAD + tid] + sPart[2 * W1PAD + tid]
              + sPart[3 * W1PAD + tid];
        sCol[tid] = v;
    }
    __syncthreads();

    const int lane = tid & 31;
    const int hl   = lane & 15;
    const int half = lane >> 4;
    const int b    = (blockIdx.x * 8 + (tid >> 5)) * 2 + half;
    const bool valid = (b < B);

    const float INIT_TH = 0.125f;
    const unsigned long long BETA2 = packx2(0.9f, 0.9f);

    // encoder state: dim d = hl + 16*j
    float r[NGRP], th[NGRP];
    const float* xb = x + (size_t)b * DDIM;
#pragma unroll
    for (int j = 0; j < NGRP; j++) {
        int d = hl + 16 * j;
        r[j]  = (valid && d < DDIM) ? xb[d] : -1.0f;   // -1: dead from start
        th[j] = INIT_TH;
    }

    const bool v01 = (hl < 13), v23 = (hl < 12);

    unsigned long long m01, m23;                 // mem1 packed pairs
    float m2 = 0.0f;
    int cnt = 0;
    unsigned alive = 0xfffu;

    const char*  wb  = (const char*)sW1 + hl * 16;
    const float* w2b = sW2 + hl * W2PAD;
    const int shamt = lane & 16;
    float* po = out + (size_t)b * CDIM + hl;
    const size_t tstride4 = (size_t)B * CDIM * sizeof(float);

    const ulonglong2 cs = *(const ulonglong2*)((const char*)sCol + hl * 16);
    float g0, g1, g2, g3;
    unpackx2(cs.x, g0, g1); unpackx2(cs.y, g2, g3);

    // ================= t = 0 (complement: ~87% spike) =================
    {
        unsigned long long c01 = 0ull, c23 = 0ull;
#pragma unroll
        for (int j = 0; j < NGRP; j++) {
            bool s = (r[j] >= th[j]);
            unsigned bal = __ballot_sync(0xffffffffu, s);
            cnt += s;
            if (s) { r[j] -= th[j]; th[j] *= 2.0f; }     // else th stays INIT
            unsigned mh = ((~bal) >> shamt) & ((j == NGRP - 1) ? 0x07ffu : 0xffffu);
            ev_accum(mh, wb + j * (16 * 208), c01, c23);
        }
        float c0, c1, c2, c3;
        unpackx2(c01, c0, c1); unpackx2(c23, c2, c3);
        float a0 = g0 - c0, a1 = g1 - c1, a2 = g2 - c2, a3 = g3 - c3;
        bool s0 = v01 && (a0 > 1.0f), s1 = v01 && (a1 > 1.0f);
        bool s2 = v23 && (a2 > 1.0f), s3 = v23 && (a3 > 1.0f);
        if (s0) a0 -= 1.0f; if (s1) a1 -= 1.0f;
        if (s2) a2 -= 1.0f; if (s3) a3 -= 1.0f;
        m01 = packx2(a0, a1); m23 = packx2(a2, a3);
        step_tail(s0, s1, s2, s3, hl, shamt, w2b, m2, valid, po, tstride4);
    }

    // ================= t = 1 (complement: ~62% spike) =================
    {
        mulx2(m01, BETA2); mulx2(m23, BETA2);
        unsigned long long c01 = 0ull, c23 = 0ull;
#pragma unroll
        for (int j = 0; j < NGRP; j++) {
            bool s = (r[j] >= th[j]);
            unsigned bal = __ballot_sync(0xffffffffu, s);
            cnt += s;
            if (s) { r[j] -= th[j]; th[j] *= 2.0f; }
            else   { th[j] = INIT_TH; }
            unsigned mh = ((~bal) >> shamt) & ((j == NGRP - 1) ? 0x07ffu : 0xffffu);
            ev_accum(mh, wb + j * (16 * 208), c01, c23);
        }
        float a0, a1, a2, a3, c0, c1, c2, c3;
        unpackx2(m01, a0, a1); unpackx2(m23, a2, a3);
        unpackx2(c01, c0, c1); unpackx2(c23, c2, c3);
        a0 += g0 - c0; a1 += g1 - c1; a2 += g2 - c2; a3 += g3 - c3;
        bool s0 = v01 && (a0 > 1.0f), s1 = v01 && (a1 > 1.0f);
        bool s2 = v23 && (a2 > 1.0f), s3 = v23 && (a3 > 1.0f);
        if (s0) a0 -= 1.0f; if (s1) a1 -= 1.0f;
        if (s2) a2 -= 1.0f; if (s3) a3 -= 1.0f;
        m01 = packx2(a0, a1); m23 = packx2(a2, a3);
        step_tail(s0, s1, s2, s3, hl, shamt, w2b, m2, valid, po, tstride4);
    }

    // ================= main loop t >= 2 (sparse + lazy death) =================
#pragma unroll 1
    for (int t = 2; t < T_STEPS; t++) {
        mulx2(m01, BETA2); mulx2(m23, BETA2);

#pragma unroll
        for (int j = 0; j < NGRP; j++) {
            const unsigned bit = 1u << j;
            if (!(alive & bit)) continue;
            bool s = (r[j] >= th[j]);
            unsigned bal = __ballot_sync(0xffffffffu, s);
            if (bal == 0u) {
                th[j] = INIT_TH;
                // exact death test only on empty steps: r<0.125 => silent forever
                unsigned ab = __ballot_sync(0xffffffffu, r[j] >= INIT_TH);
                if (ab == 0u) alive &= ~bit;
                continue;
            }
            cnt += s;
            if (s) { r[j] -= th[j]; th[j] *= 2.0f; }
            else   { th[j] = INIT_TH; }
            unsigned mh = (bal >> shamt) & 0xffffu;
            ev_accum(mh, wb + j * (16 * 208), m01, m23);
        }

        float a0, a1, a2, a3;
        unpackx2(m01, a0, a1); unpackx2(m23, a2, a3);
        bool s0 = v01 && (a0 > 1.0f), s1 = v01 && (a1 > 1.0f);
        bool s2 = v23 && (a2 > 1.0f), s3 = v23 && (a3 > 1.0f);
        if (s0) a0 -= 1.0f; if (s1) a1 -= 1.0f;
        if (s2) a2 -= 1.0f; if (s3) a3 -= 1.0f;
        m01 = packx2(a0, a1); m23 = packx2(a2, a3);

        unsigned any = step_tail(s0, s1, s2, s3, hl, shamt, w2b, m2,
                                 valid, po, tstride4);
        if (alive == 0u && any == 0u) break;     // provably all-zero from here
    }

    // -------- spike counts (exact integer, reduce within half) --------
#pragma unroll
    for (int off = 8; off; off >>= 1)
        cnt += __shfl_xor_sync(0xffffffffu, cnt, off);
    if (valid && hl == 0)
        out[(size_t)T_STEPS * B * CDIM + b] = (float)cnt;
}

extern "C" void kernel_launch(void* const* d_in, const int* in_sizes, int n_in,
                              void* d_out, int out_size)
{
    const float* x  = (const float*)d_in[0];
    const float* W1 = (const float*)d_in[1];
    const float* W2 = (const float*)d_in[2];
    float* out = (float*)d_out;

    int B = in_sizes[0] / DDIM;
    // pre-zero spk_rec [32,B,5]; counts fully written by kernel
    cudaMemsetAsync(out, 0, (size_t)T_STEPS * B * CDIM * sizeof(float));
    int blocks = (B + 15) / 16;   // 8 warps/block, 2 samples/warp
    burst_snn_kernel<<<blocks, 256>>>(x, W1, W2, out, B);
}